// round 1
// baseline (speedup 1.0000x reference)
#include <cuda_runtime.h>

#define BATCH 8
#define SEQ 1024
#define HID 1024
#define D2 128
#define NHEADS 12
#define NC 24

typedef unsigned long long u64;

// ---------------- scratch (device globals; no allocation) ----------------
__device__ float g_h[BATCH * SEQ * D2];        // 4 MB
__device__ float g_qT[BATCH * 64 * SEQ];       // 2 MB, layout [b][d][s], pre-scaled by 1/8
__device__ float g_kT[BATCH * 64 * SEQ];       // 2 MB, layout [b][d][s]
__device__ float g_bias[BATCH * NC * SEQ];     // 0.75 MB, layout [b][c][s], already (h@W2+b2)/2

// ---------------- f32x2 helpers (Blackwell packed fp32) ----------------
__device__ __forceinline__ u64 pack2(float lo, float hi) {
    u64 r; asm("mov.b64 %0, {%1,%2};" : "=l"(r) : "f"(lo), "f"(hi)); return r;
}
__device__ __forceinline__ void unpack2(u64 v, float& lo, float& hi) {
    asm("mov.b64 {%0,%1}, %2;" : "=f"(lo), "=f"(hi) : "l"(v));
}
__device__ __forceinline__ void fma2(u64& d, u64 a, u64 b) {
    asm("fma.rn.f32x2 %0, %1, %2, %0;" : "+l"(d) : "l"(a), "l"(b));
}

// ---------------- kernel 1: h = X @ W1 + b1  (8192x128, K=1024) ----------------
__global__ __launch_bounds__(256) void gemm1_kernel(const float* __restrict__ X,
                                                    const float* __restrict__ W1,
                                                    const float* __restrict__ b1) {
    __shared__ float As[32][68];    // transposed X tile: As[k][m]
    __shared__ float Bs[32][128];   // W1 tile: Bs[k][n]
    const int t = threadIdx.x;
    const int m0 = blockIdx.x * 64;
    const int tm = t >> 4, tn = t & 15;
    const int ml = tm * 4, nl = tn * 8;

    u64 acc[2][8];
#pragma unroll
    for (int j = 0; j < 8; j++) {
        float bv = b1[nl + j];
        u64 p = pack2(bv, bv);
        acc[0][j] = p; acc[1][j] = p;
    }

    for (int k0 = 0; k0 < HID; k0 += 32) {
#pragma unroll
        for (int u = 0; u < 2; u++) {
            int idx = t + 256 * u;
            int ar = idx >> 3, kq = (idx & 7) * 4;
            float4 a = *(const float4*)&X[(size_t)(m0 + ar) * HID + k0 + kq];
            As[kq + 0][ar] = a.x; As[kq + 1][ar] = a.y;
            As[kq + 2][ar] = a.z; As[kq + 3][ar] = a.w;
        }
#pragma unroll
        for (int u = 0; u < 4; u++) {
            int idx = t + 256 * u;
            int kb = idx >> 5, nq = (idx & 31) * 4;
            *(float4*)&Bs[kb][nq] = *(const float4*)&W1[(size_t)(k0 + kb) * D2 + nq];
        }
        __syncthreads();
#pragma unroll 8
        for (int kk = 0; kk < 32; kk++) {
            float4 a4 = *(float4*)&As[kk][ml];
            u64 ap0 = pack2(a4.x, a4.y), ap1 = pack2(a4.z, a4.w);
            float4 b4a = *(float4*)&Bs[kk][nl];
            float4 b4b = *(float4*)&Bs[kk][nl + 4];
            float bv[8] = {b4a.x, b4a.y, b4a.z, b4a.w, b4b.x, b4b.y, b4b.z, b4b.w};
#pragma unroll
            for (int j = 0; j < 8; j++) {
                u64 bd = pack2(bv[j], bv[j]);
                fma2(acc[0][j], ap0, bd);
                fma2(acc[1][j], ap1, bd);
            }
        }
        __syncthreads();
    }

#pragma unroll
    for (int p = 0; p < 2; p++) {
        float lo[8], hi[8];
#pragma unroll
        for (int j = 0; j < 8; j++) unpack2(acc[p][j], lo[j], hi[j]);
        size_t r0 = (size_t)(m0 + ml + 2 * p) * D2 + nl;
        *(float4*)&g_h[r0]          = make_float4(lo[0], lo[1], lo[2], lo[3]);
        *(float4*)&g_h[r0 + 4]      = make_float4(lo[4], lo[5], lo[6], lo[7]);
        *(float4*)&g_h[r0 + D2]     = make_float4(hi[0], hi[1], hi[2], hi[3]);
        *(float4*)&g_h[r0 + D2 + 4] = make_float4(hi[4], hi[5], hi[6], hi[7]);
    }
}

// ---------------- kernel 2: RoPE(q,k) transposed + bias = (h@W2+b2)/2 ----------------
__global__ __launch_bounds__(256) void ropebias_kernel(const float* __restrict__ W2,
                                                       const float* __restrict__ b2) {
    __shared__ float hs[32][132];
    __shared__ float ws[D2 * NC];
    const int t = threadIdx.x;
    const int r0 = blockIdx.x * 32;        // global row (b*1024+s) base
    const int b = r0 >> 10;
    const int s0 = r0 & 1023;

#pragma unroll
    for (int u = 0; u < 4; u++) {
        int idx = t + 256 * u;
        int sr = idx >> 5, jq = (idx & 31) * 4;
        *(float4*)&hs[sr][jq] = *(const float4*)&g_h[(size_t)(r0 + sr) * D2 + jq];
    }
#pragma unroll
    for (int u = 0; u < 12; u++) ws[t + 256 * u] = W2[t + 256 * u];
    __syncthreads();

    const int sl = t & 31;
    const int s = s0 + sl;
    const int dbase = t >> 5;
#pragma unroll
    for (int it = 0; it < 8; it++) {
        int d = dbase + it * 8;            // 0..63
        int j = d >> 1;                    // rope pair index
        double angd = (double)s * exp(-(double)(2 * j) / 64.0 * 9.210340371976184);
        double sd, cd;
        sincos(angd, &sd, &cd);
        float sn = (float)sd, cs = (float)cd;
        // q[d] = h[2d]; rope pair (q[2j], q[2j+1]) = (h[4j], h[4j+2])
        float qA = hs[sl][4 * j],     qB = hs[sl][4 * j + 2];
        float kA = hs[sl][4 * j + 1], kB = hs[sl][4 * j + 3];
        float qv, kv;
        if (d & 1) { qv = qB * cs + qA * sn; kv = kB * cs + kA * sn; }
        else       { qv = qA * cs - qB * sn; kv = kA * cs - kB * sn; }
        g_qT[(size_t)(b * 64 + d) * SEQ + s] = qv * 0.125f;   // fold 1/sqrt(64)
        g_kT[(size_t)(b * 64 + d) * SEQ + s] = kv;
    }

    for (int cc = t >> 5; cc < NC; cc += 8) {
        float dot = b2[cc];
#pragma unroll
        for (int j = 0; j < D2; j += 4) {
            float4 h4 = *(float4*)&hs[sl][j];
            dot += h4.x * ws[(j + 0) * NC + cc] + h4.y * ws[(j + 1) * NC + cc]
                 + h4.z * ws[(j + 2) * NC + cc] + h4.w * ws[(j + 3) * NC + cc];
        }
        g_bias[(size_t)(b * NC + cc) * SEQ + s] = dot * 0.5f;
    }
}

// ---------------- kernel 3: logits = att + bq[m] + bk[n] with mask/row0/col0/tril ----------------
__global__ __launch_bounds__(256) void logits_kernel(const float* __restrict__ am,
                                                     float* __restrict__ out) {
    __shared__ float qs[64][64];          // [d][m]; reused as att[m][n] after compute
    __shared__ float ks[64][64];          // [d][n]
    __shared__ float bq[NHEADS][64];
    __shared__ float bk[NHEADS][64];
    __shared__ float amm[64], amn[64];
    __shared__ int s_maskone;

    const int t = threadIdx.x;
    const int b = blockIdx.z, mt = blockIdx.y, nt = blockIdx.x;
    const int m0 = mt * 64, n0 = nt * 64;

#pragma unroll
    for (int u = 0; u < 4; u++) {
        int idx = t + 256 * u;
        int d = idx >> 4, mq = (idx & 15) * 4;
        *(float4*)&qs[d][mq] = *(const float4*)&g_qT[(size_t)(b * 64 + d) * SEQ + m0 + mq];
        *(float4*)&ks[d][mq] = *(const float4*)&g_kT[(size_t)(b * 64 + d) * SEQ + n0 + mq];
    }
    if (t < 192) {
        int h = t >> 4, mq = (t & 15) * 4;
        *(float4*)&bq[h][mq] = *(const float4*)&g_bias[(size_t)(b * NC + 2 * h) * SEQ + m0 + mq];
        *(float4*)&bk[h][mq] = *(const float4*)&g_bias[(size_t)(b * NC + 2 * h + 1) * SEQ + n0 + mq];
    } else if (t < 208) {
        int u = t - 192; *(float4*)&amm[u * 4] = *(const float4*)&am[b * SEQ + m0 + u * 4];
    } else if (t < 224) {
        int u = t - 208; *(float4*)&amn[u * 4] = *(const float4*)&am[b * SEQ + n0 + u * 4];
    }
    __syncthreads();
    if (t == 0) {
        int ok = 1;
        for (int i = 0; i < 64; i++) ok &= (amm[i] == 1.0f) & (amn[i] == 1.0f);
        s_maskone = ok;
    }

    // att tile: thread computes 4m x 4n, packed along n pairs
    const int tm = t >> 4, tn = t & 15;
    const int ml = tm * 4, nl = tn * 4;
    u64 acc[4][2];
    u64 z = pack2(0.0f, 0.0f);
#pragma unroll
    for (int i = 0; i < 4; i++) { acc[i][0] = z; acc[i][1] = z; }

#pragma unroll 8
    for (int d = 0; d < 64; d++) {
        float4 q4 = *(float4*)&qs[d][ml];
        float4 k4 = *(float4*)&ks[d][nl];
        u64 kp0 = pack2(k4.x, k4.y), kp1 = pack2(k4.z, k4.w);
        u64 q0 = pack2(q4.x, q4.x), q1 = pack2(q4.y, q4.y);
        u64 q2 = pack2(q4.z, q4.z), q3 = pack2(q4.w, q4.w);
        fma2(acc[0][0], q0, kp0); fma2(acc[0][1], q0, kp1);
        fma2(acc[1][0], q1, kp0); fma2(acc[1][1], q1, kp1);
        fma2(acc[2][0], q2, kp0); fma2(acc[2][1], q2, kp1);
        fma2(acc[3][0], q3, kp0); fma2(acc[3][1], q3, kp1);
    }
    __syncthreads();                       // everyone done reading qs/ks
    float (*atts)[64] = qs;                // reuse q tile smem for att[m][n]
#pragma unroll
    for (int i = 0; i < 4; i++) {
        *(u64*)&atts[ml + i][nl]     = acc[i][0];
        *(u64*)&atts[ml + i][nl + 2] = acc[i][1];
    }
    __syncthreads();

    const int maskone = s_maskone;
    const bool mt0 = (m0 == 0), nt0 = (n0 == 0);
    const bool allT = (m0 > n0 + 63);
    const bool anyT = (m0 + 63 > n0);
    const float NEG = -10000.0f, BIG = 1e12f;

    for (int h = 0; h < NHEADS; h++) {
        size_t base = (((size_t)(b * NHEADS + h)) * SEQ + m0) * SEQ + n0;
#pragma unroll
        for (int i = 0; i < 4; i++) {
            int idx = t + 256 * i;
            int m = idx >> 4, n = (idx & 15) * 4;
            float4 a4 = *(float4*)&atts[m][n];
            float bb = bq[h][m];
            float4 c4 = *(float4*)&bk[h][n];
            float4 v;
            v.x = a4.x + bb + c4.x; v.y = a4.y + bb + c4.y;
            v.z = a4.z + bb + c4.z; v.w = a4.w + bb + c4.w;
            if (!maskone) {
                float amv = amm[m];
                v.x -= (1.0f - amv * amn[n + 0]) * BIG;
                v.y -= (1.0f - amv * amn[n + 1]) * BIG;
                v.z -= (1.0f - amv * amn[n + 2]) * BIG;
                v.w -= (1.0f - amv * amn[n + 3]) * BIG;
            }
            if (mt0 && m == 0) { v.x = NEG; v.y = NEG; v.z = NEG; v.w = NEG; }
            if (nt0 && n == 0) v.x = NEG;
            if (allT) { v.x -= BIG; v.y -= BIG; v.z -= BIG; v.w -= BIG; }
            else if (anyT) {
                int gm = m0 + m, gn = n0 + n;
                if (gm > gn)     v.x -= BIG;
                if (gm > gn + 1) v.y -= BIG;
                if (gm > gn + 2) v.z -= BIG;
                if (gm > gn + 3) v.w -= BIG;
            }
            __stcs((float4*)(out + base + (size_t)m * SEQ + n), v);
        }
    }
}

// ---------------- launch ----------------
extern "C" void kernel_launch(void* const* d_in, const int* in_sizes, int n_in,
                              void* d_out, int out_size) {
    const float* X  = (const float*)d_in[0];
    const float* am = (const float*)d_in[1];
    const float* W1 = (const float*)d_in[2];
    const float* b1 = (const float*)d_in[3];
    const float* W2 = (const float*)d_in[4];
    const float* b2 = (const float*)d_in[5];
    float* out = (float*)d_out;

    gemm1_kernel<<<(BATCH * SEQ) / 64, 256>>>(X, W1, b1);
    ropebias_kernel<<<(BATCH * SEQ) / 32, 256>>>(W2, b2);
    dim3 g3(SEQ / 64, SEQ / 64, BATCH);
    logits_kernel<<<g3, 256>>>(am, out);
}

// round 2
// speedup vs baseline: 1.6686x; 1.6686x over previous
#include <cuda_runtime.h>

#define BATCH 8
#define SEQ 1024
#define HID 1024
#define D2 128
#define NHEADS 12
#define NC 24

typedef unsigned long long u64;

// ---------------- scratch (device globals; no allocation) ----------------
__device__ float g_h[BATCH * SEQ * D2];        // 4 MB
__device__ float g_qT[BATCH * 64 * SEQ];       // 2 MB, layout [b][d][s], pre-scaled by 1/8
__device__ float g_kT[BATCH * 64 * SEQ];       // 2 MB, layout [b][d][s]
__device__ float g_bias[BATCH * NC * SEQ];     // 0.75 MB, layout [b][c][s], already (h@W2+b2)/2

// ---------------- f32x2 helpers (Blackwell packed fp32) ----------------
__device__ __forceinline__ u64 pack2(float lo, float hi) {
    u64 r; asm("mov.b64 %0, {%1,%2};" : "=l"(r) : "f"(lo), "f"(hi)); return r;
}
__device__ __forceinline__ void unpack2(u64 v, float& lo, float& hi) {
    asm("mov.b64 {%0,%1}, %2;" : "=f"(lo), "=f"(hi) : "l"(v));
}
__device__ __forceinline__ void fma2(u64& d, u64 a, u64 b) {
    asm("fma.rn.f32x2 %0, %1, %2, %0;" : "+l"(d) : "l"(a), "l"(b));
}

// ---------------- cp.async helpers ----------------
__device__ __forceinline__ void cpa16(void* s, const void* g) {
    unsigned sa = (unsigned)__cvta_generic_to_shared(s);
    asm volatile("cp.async.cg.shared.global [%0], [%1], 16;\n" :: "r"(sa), "l"(g));
}
__device__ __forceinline__ void cpa_commit() { asm volatile("cp.async.commit_group;\n" ::: "memory"); }
template<int N> __device__ __forceinline__ void cpa_wait() {
    asm volatile("cp.async.wait_group %0;\n" :: "n"(N) : "memory");
}

// ---------------- kernel 1: h = X @ W1 + b1  (8192x128, K=1024) ----------------
// 512 threads, M-tile 64, K staged x32, cp.async double buffer.
__global__ __launch_bounds__(512) void gemm1_kernel(const float* __restrict__ X,
                                                    const float* __restrict__ W1,
                                                    const float* __restrict__ b1) {
    __shared__ float As[2][64][32];    // [m][k], rows broadcast-read
    __shared__ float Bs[2][32][128];   // [k][n]
    const int t = threadIdx.x;
    const int m0 = blockIdx.x * 64;
    const int tm = t >> 5, tn = t & 31;
    const int ml = tm * 4, nl = tn * 4;

    // per-thread cp.async source/dest coords (constant across stages)
    const int a_m = t >> 3, a_q = (t & 7) * 4;                 // A: 512 chunks
    const int b_r0 = t >> 5, b_c0 = (t & 31) * 4;              // B chunk 1
    const int b_r1 = (t + 512) >> 5, b_c1 = b_c0;              // B chunk 2 (rows 16..31)

    auto load_stage = [&](int buf, int k0) {
        cpa16(&As[buf][a_m][a_q], &X[(size_t)(m0 + a_m) * HID + k0 + a_q]);
        cpa16(&Bs[buf][b_r0][b_c0], &W1[(size_t)(k0 + b_r0) * D2 + b_c0]);
        cpa16(&Bs[buf][b_r1][b_c1], &W1[(size_t)(k0 + b_r1) * D2 + b_c1]);
        cpa_commit();
    };

    u64 acc[4][2];
    {
        float4 bv = *(const float4*)&b1[nl];
        u64 p0 = pack2(bv.x, bv.y), p1 = pack2(bv.z, bv.w);
#pragma unroll
        for (int i = 0; i < 4; i++) { acc[i][0] = p0; acc[i][1] = p1; }
    }

    load_stage(0, 0);

    const int NSTAGE = HID / 32;
    for (int s = 0; s < NSTAGE; s++) {
        if (s + 1 < NSTAGE) { load_stage((s + 1) & 1, (s + 1) * 32); cpa_wait<1>(); }
        else                { cpa_wait<0>(); }
        __syncthreads();

        const float (*A)[32] = As[s & 1];
        const float (*B)[128] = Bs[s & 1];
#pragma unroll
        for (int kk = 0; kk < 32; kk++) {
            float a0 = A[ml + 0][kk], a1 = A[ml + 1][kk];
            float a2 = A[ml + 2][kk], a3 = A[ml + 3][kk];
            ulonglong2 bb = *(const ulonglong2*)&B[kk][nl];
            u64 d0 = pack2(a0, a0), d1 = pack2(a1, a1);
            u64 d2 = pack2(a2, a2), d3 = pack2(a3, a3);
            fma2(acc[0][0], d0, bb.x); fma2(acc[0][1], d0, bb.y);
            fma2(acc[1][0], d1, bb.x); fma2(acc[1][1], d1, bb.y);
            fma2(acc[2][0], d2, bb.x); fma2(acc[2][1], d2, bb.y);
            fma2(acc[3][0], d3, bb.x); fma2(acc[3][1], d3, bb.y);
        }
        __syncthreads();
    }

#pragma unroll
    for (int i = 0; i < 4; i++) {
        float x0, x1, x2, x3;
        unpack2(acc[i][0], x0, x1);
        unpack2(acc[i][1], x2, x3);
        *(float4*)&g_h[(size_t)(m0 + ml + i) * D2 + nl] = make_float4(x0, x1, x2, x3);
    }
}

// ---------------- kernel 2: RoPE(q,k) transposed + bias = (h@W2+b2)/2 ----------------
__global__ __launch_bounds__(256) void ropebias_kernel(const float* __restrict__ W2,
                                                       const float* __restrict__ b2) {
    __shared__ float hs[32][132];
    __shared__ float ws[D2 * NC];
    const int t = threadIdx.x;
    const int r0 = blockIdx.x * 32;        // global row (b*1024+s) base
    const int b = r0 >> 10;
    const int s0 = r0 & 1023;

#pragma unroll
    for (int u = 0; u < 4; u++) {
        int idx = t + 256 * u;
        int sr = idx >> 5, jq = (idx & 31) * 4;
        *(float4*)&hs[sr][jq] = *(const float4*)&g_h[(size_t)(r0 + sr) * D2 + jq];
    }
#pragma unroll
    for (int u = 0; u < 12; u++) ws[t + 256 * u] = W2[t + 256 * u];
    __syncthreads();

    const int sl = t & 31;
    const int s = s0 + sl;
    const int dbase = t >> 5;
#pragma unroll
    for (int it = 0; it < 8; it++) {
        int d = dbase + it * 8;            // 0..63
        int j = d >> 1;                    // rope pair index
        // inv_freq = 10000^(-2j/64), fp32 (matches the fp32 reference)
        float inv = exp2f((float)(2 * j) * (-13.287712379549449f / 64.0f));
        float ang = (float)s * inv;
        float sn, cs;
        sincosf(ang, &sn, &cs);
        // q[d] = h[2d]; rope pair (q[2j], q[2j+1]) = (h[4j], h[4j+2])
        float qA = hs[sl][4 * j],     qB = hs[sl][4 * j + 2];
        float kA = hs[sl][4 * j + 1], kB = hs[sl][4 * j + 3];
        float qv, kv;
        if (d & 1) { qv = qB * cs + qA * sn; kv = kB * cs + kA * sn; }
        else       { qv = qA * cs - qB * sn; kv = kA * cs - kB * sn; }
        g_qT[(size_t)(b * 64 + d) * SEQ + s] = qv * 0.125f;   // fold 1/sqrt(64)
        g_kT[(size_t)(b * 64 + d) * SEQ + s] = kv;
    }

    for (int cc = t >> 5; cc < NC; cc += 8) {
        float dot = b2[cc];
#pragma unroll
        for (int j = 0; j < D2; j += 4) {
            float4 h4 = *(float4*)&hs[sl][j];
            dot += h4.x * ws[(j + 0) * NC + cc] + h4.y * ws[(j + 1) * NC + cc]
                 + h4.z * ws[(j + 2) * NC + cc] + h4.w * ws[(j + 3) * NC + cc];
        }
        g_bias[(size_t)(b * NC + cc) * SEQ + s] = dot * 0.5f;
    }
}

// ---------------- kernel 3: logits = att + bq[m] + bk[n] with mask/row0/col0/tril ----------------
__global__ __launch_bounds__(256) void logits_kernel(const float* __restrict__ am,
                                                     float* __restrict__ out) {
    __shared__ float qs[64][64];          // [d][m]; reused as att[m][n] after compute
    __shared__ float ks[64][64];          // [d][n]
    __shared__ float bq[NHEADS][64];
    __shared__ float bk[NHEADS][64];
    __shared__ float amm[64], amn[64];
    __shared__ int s_maskone;

    const int t = threadIdx.x;
    const int b = blockIdx.z, mt = blockIdx.y, nt = blockIdx.x;
    const int m0 = mt * 64, n0 = nt * 64;

#pragma unroll
    for (int u = 0; u < 4; u++) {
        int idx = t + 256 * u;
        int d = idx >> 4, mq = (idx & 15) * 4;
        *(float4*)&qs[d][mq] = *(const float4*)&g_qT[(size_t)(b * 64 + d) * SEQ + m0 + mq];
        *(float4*)&ks[d][mq] = *(const float4*)&g_kT[(size_t)(b * 64 + d) * SEQ + n0 + mq];
    }
    if (t < 192) {
        int h = t >> 4, mq = (t & 15) * 4;
        *(float4*)&bq[h][mq] = *(const float4*)&g_bias[(size_t)(b * NC + 2 * h) * SEQ + m0 + mq];
        *(float4*)&bk[h][mq] = *(const float4*)&g_bias[(size_t)(b * NC + 2 * h + 1) * SEQ + n0 + mq];
    } else if (t < 208) {
        int u = t - 192; *(float4*)&amm[u * 4] = *(const float4*)&am[b * SEQ + m0 + u * 4];
    } else if (t < 224) {
        int u = t - 208; *(float4*)&amn[u * 4] = *(const float4*)&am[b * SEQ + n0 + u * 4];
    }
    __syncthreads();
    if (t == 0) {
        int ok = 1;
        for (int i = 0; i < 64; i++) ok &= (amm[i] == 1.0f) & (amn[i] == 1.0f);
        s_maskone = ok;
    }

    // att tile: thread computes 4m x 4n, packed along n pairs
    const int tm = t >> 4, tn = t & 15;
    const int ml = tm * 4, nl = tn * 4;
    u64 acc[4][2];
    u64 z = pack2(0.0f, 0.0f);
#pragma unroll
    for (int i = 0; i < 4; i++) { acc[i][0] = z; acc[i][1] = z; }

#pragma unroll 8
    for (int d = 0; d < 64; d++) {
        float4 q4 = *(float4*)&qs[d][ml];
        ulonglong2 kp = *(const ulonglong2*)&ks[d][nl];
        u64 q0 = pack2(q4.x, q4.x), q1 = pack2(q4.y, q4.y);
        u64 q2 = pack2(q4.z, q4.z), q3 = pack2(q4.w, q4.w);
        fma2(acc[0][0], q0, kp.x); fma2(acc[0][1], q0, kp.y);
        fma2(acc[1][0], q1, kp.x); fma2(acc[1][1], q1, kp.y);
        fma2(acc[2][0], q2, kp.x); fma2(acc[2][1], q2, kp.y);
        fma2(acc[3][0], q3, kp.x); fma2(acc[3][1], q3, kp.y);
    }
    __syncthreads();                       // everyone done reading qs/ks
    float (*atts)[64] = qs;                // reuse q tile smem for att[m][n]
#pragma unroll
    for (int i = 0; i < 4; i++) {
        *(u64*)&atts[ml + i][nl]     = acc[i][0];
        *(u64*)&atts[ml + i][nl + 2] = acc[i][1];
    }
    __syncthreads();

    const int maskone = s_maskone;
    const bool mt0 = (m0 == 0), nt0 = (n0 == 0);
    const bool allT = (m0 > n0 + 63);
    const bool anyT = (m0 + 63 > n0);
    const float NEG = -10000.0f, BIG = 1e12f;

    for (int h = 0; h < NHEADS; h++) {
        size_t base = (((size_t)(b * NHEADS + h)) * SEQ + m0) * SEQ + n0;
#pragma unroll
        for (int i = 0; i < 4; i++) {
            int idx = t + 256 * i;
            int m = idx >> 4, n = (idx & 15) * 4;
            float4 a4 = *(float4*)&atts[m][n];
            float bb = bq[h][m];
            float4 c4 = *(float4*)&bk[h][n];
            float4 v;
            v.x = a4.x + bb + c4.x; v.y = a4.y + bb + c4.y;
            v.z = a4.z + bb + c4.z; v.w = a4.w + bb + c4.w;
            if (!maskone) {
                float amv = amm[m];
                v.x -= (1.0f - amv * amn[n + 0]) * BIG;
                v.y -= (1.0f - amv * amn[n + 1]) * BIG;
                v.z -= (1.0f - amv * amn[n + 2]) * BIG;
                v.w -= (1.0f - amv * amn[n + 3]) * BIG;
            }
            if (mt0 && m == 0) { v.x = NEG; v.y = NEG; v.z = NEG; v.w = NEG; }
            if (nt0 && n == 0) v.x = NEG;
            if (allT) { v.x -= BIG; v.y -= BIG; v.z -= BIG; v.w -= BIG; }
            else if (anyT) {
                int gm = m0 + m, gn = n0 + n;
                if (gm > gn)     v.x -= BIG;
                if (gm > gn + 1) v.y -= BIG;
                if (gm > gn + 2) v.z -= BIG;
                if (gm > gn + 3) v.w -= BIG;
            }
            __stcs((float4*)(out + base + (size_t)m * SEQ + n), v);
        }
    }
}

// ---------------- launch ----------------
extern "C" void kernel_launch(void* const* d_in, const int* in_sizes, int n_in,
                              void* d_out, int out_size) {
    const float* X  = (const float*)d_in[0];
    const float* am = (const float*)d_in[1];
    const float* W1 = (const float*)d_in[2];
    const float* b1 = (const float*)d_in[3];
    const float* W2 = (const float*)d_in[4];
    const float* b2 = (const float*)d_in[5];
    float* out = (float*)d_out;

    gemm1_kernel<<<(BATCH * SEQ) / 64, 512>>>(X, W1, b1);
    ropebias_kernel<<<(BATCH * SEQ) / 32, 256>>>(W2, b2);
    dim3 g3(SEQ / 64, SEQ / 64, BATCH);
    logits_kernel<<<g3, 256>>>(am, out);
}